// round 16
// baseline (speedup 1.0000x reference)
#include <cuda_runtime.h>
#include <math.h>

#define BB 128
#define NN 128
#define RT 16
#define RGF (NN / RT)   // 8: fold-column index in edge grid

// Folded fo + head weights (written by edge kernel's piggyback blocks).
struct QWeights {
    float Wo1s[22][48];   // [j][k]: j<16 scaled x256, j=16..21 x1; k>=45 pad 0
    float bo1[48];
    float Wo2s[45][24];   // [j][k], k>=22 pad 0
    float bo2[24];
    float Wo3s[22][8];    // [j][c], c>=6 pad 0
    float bo3[8];
    float Wc1t[48][8];
    float bc1[48];
    float Wc2t[5][48];
    float bc2[8];
};

__device__ QWeights g_qw;
__device__ __align__(16) float g_bn[BB * NN * 16];
__device__ __align__(16) float g_eff[BB * NN * 6];

__device__ __forceinline__ float qb(float x) {
    float y = fminf(fmaxf(x, -1.0f), 127.0f / 128.0f);
    return rintf(y * 128.0f) * (1.0f / 128.0f);
}
__device__ __forceinline__ int qm(float x) {
    float y = fminf(fmaxf(x, -1.0f), 127.0f / 128.0f);
    return (int)rintf(y * 128.0f);
}
__device__ __forceinline__ float qreluF(float p) {
    return rintf(fminf(fmaxf(p, 0.0f), 255.0f));
}
__device__ __forceinline__ unsigned cvt_u8(float x) {
    unsigned short h;
    asm("cvt.rni.sat.u8.f32 %0, %1;" : "=h"(h) : "f"(x));
    return (unsigned)h;
}
__device__ __forceinline__ unsigned requant(int acc) {
    return cvt_u8((float)acc * (1.0f / 128.0f));
}
__device__ __forceinline__ unsigned pk4(unsigned a, unsigned b, unsigned c, unsigned d) {
    return __byte_perm(__byte_perm(a, b, 0x0040), __byte_perm(c, d, 0x0040), 0x5410);
}
__device__ __forceinline__ int dp4a_us(unsigned a, unsigned b, int c) {
    int d;
    asm("dp4a.u32.s32 %0, %1, %2, %3;" : "=r"(d) : "r"(a), "r"(b), "r"(c));
    return d;
}

// ---------------------------------------------------------------------------
// edge kernel: grid (RGF+1, BB) — UNCHANGED from the 59.5us version.
//   rg < RGF : edge path (bn/Ar/As inline, dp4a main loop -> g_eff)
//   rg == RGF, b < 4 : fold fo + head weights -> g_qw
// ---------------------------------------------------------------------------
struct EdgeW { unsigned W2p[15][8]; int b2i[16]; unsigned W3p[6][4]; int b3i[8]; };

__global__ void __launch_bounds__(128) edge_kernel(
    const float* __restrict__ x,
    const float* __restrict__ gamma, const float* __restrict__ beta,
    const float* __restrict__ mean,  const float* __restrict__ var,
    const float* __restrict__ fr_w1, const float* __restrict__ fr_b1,
    const float* __restrict__ fr_w2, const float* __restrict__ fr_b2,
    const float* __restrict__ fr_w3, const float* __restrict__ fr_b3,
    const float* __restrict__ fo_w1, const float* __restrict__ fo_b1,
    const float* __restrict__ fo_w2, const float* __restrict__ fo_b2,
    const float* __restrict__ fo_w3, const float* __restrict__ fo_b3,
    const float* __restrict__ fc_w1, const float* __restrict__ fc_b1,
    const float* __restrict__ fc_w2, const float* __restrict__ fc_b2)
{
    const int t = threadIdx.x;
    const int rg = blockIdx.x, b = blockIdx.y;

    if (rg == RGF) {
        if (b == 0) {
            for (int i = t; i < 22 * 48; i += 128) {
                int j = i / 48, k = i % 48;
                float v = (k < 45) ? qb(fo_w1[j * 45 + k]) : 0.0f;
                g_qw.Wo1s[j][k] = (j < 16) ? 256.0f * v : v;
            }
            if (t < 48) g_qw.bo1[t] = (t < 45) ? 256.0f * qb(fo_b1[t]) : 0.0f;
        } else if (b == 1) {
            for (int i = t; i < 45 * 24; i += 128) {
                int j = i / 24, k = i % 24;
                g_qw.Wo2s[j][k] = (k < 22) ? qb(fo_w2[j * 22 + k]) : 0.0f;
            }
            if (t < 24) g_qw.bo2[t] = (t < 22) ? 256.0f * qb(fo_b2[t]) : 0.0f;
        } else if (b == 2) {
            for (int i = t; i < 22 * 8; i += 128) {
                int j = i / 8, c = i % 8;
                g_qw.Wo3s[j][c] = (c < 6) ? qb(fo_w3[j * 6 + c]) : 0.0f;
            }
            if (t < 8) g_qw.bo3[t] = (t < 6) ? 256.0f * qb(fo_b3[t]) : 0.0f;
            for (int i = t; i < 48 * 8; i += 128) {
                int k = i / 8, c = i % 8;
                g_qw.Wc1t[k][c] = (c < 6) ? qb(fc_w1[c * 48 + k]) : 0.0f;
            }
            if (t < 48) g_qw.bc1[t] = 256.0f * qb(fc_b1[t]);
        } else if (b == 3) {
            for (int i = t; i < 5 * 48; i += 128) {
                int o = i / 48, k = i % 48;
                g_qw.Wc2t[o][k] = qb(fc_w2[k * 5 + o]) * (1.0f / 256.0f);
            }
            if (t < 8) g_qw.bc2[t] = (t < 5) ? qb(fc_b2[t]) : 0.0f;
        }
        return;
    }

    __shared__ __align__(16) float sW1[32 * 32];
    __shared__ float sb1[32];
    __shared__ float sA[16], sB[16];
    __shared__ float sBn[NN][17];
    __shared__ __align__(16) EdgeW sEw;
    __shared__ __align__(16) float sAr[RT][36];
    __shared__ int sEffI[RT][4];

    const int r0 = rg * RT;

    for (int i = t; i < 1024; i += 128) {
        int j = i >> 5, k = i & 31;
        sW1[i] = (k < 30) ? 256.0f * qb(fr_w1[j * 30 + k]) : 0.0f;
    }
    if (t < 120) {
        int k = t / 8, j4 = t % 8;
        unsigned p = 0;
#pragma unroll
        for (int u = 0; u < 4; u++) {
            int j = j4 * 4 + u;
            int m = (j < 30) ? qm(fr_w2[j * 15 + k]) : 0;
            p |= ((unsigned)(m & 255)) << (8 * u);
        }
        sEw.W2p[k][j4] = p;
    }
    if (t >= 120 && t < 126) sEw.b3i[t - 120] = 256 * qm(fr_b3[t - 120]);
    if (t < 24) {
        int c = t / 4, j4 = t % 4;
        unsigned p = 0;
#pragma unroll
        for (int u = 0; u < 4; u++) {
            int j = j4 * 4 + u;
            int m = (j < 15) ? qm(fr_w3[j * 6 + c]) : 0;
            p |= ((unsigned)(m & 255)) << (8 * u);
        }
        sEw.W3p[c][j4] = p;
    }
    if (t < 16) sEw.b2i[t] = (t < 15) ? 256 * qm(fr_b2[t]) : 0;
    if (t < 32) sb1[t] = (t < 30) ? 256.0f * qb(fr_b1[t]) : 0.0f;
    if (t < 16) {
        float s = gamma[t] / sqrtf(var[t] + 1e-3f);
        sA[t] = s;
        sB[t] = beta[t] - mean[t] * s;
    }
    if (t < RT * 4) (&sEffI[0][0])[t] = 0;
    __syncthreads();

    float bn[16];
    {
        const float4* xp = reinterpret_cast<const float4*>(x + (size_t)(b * NN + t) * 16);
#pragma unroll
        for (int i = 0; i < 4; i++) {
            float4 v = xp[i];
            bn[4 * i + 0] = v.x * sA[4 * i + 0] + sB[4 * i + 0];
            bn[4 * i + 1] = v.y * sA[4 * i + 1] + sB[4 * i + 1];
            bn[4 * i + 2] = v.z * sA[4 * i + 2] + sB[4 * i + 2];
            bn[4 * i + 3] = v.w * sA[4 * i + 3] + sB[4 * i + 3];
        }
#pragma unroll
        for (int j = 0; j < 16; j++) sBn[t][j] = bn[j];
        if (rg == 0) {
            float4* bno = reinterpret_cast<float4*>(&g_bn[(size_t)(b * NN + t) * 16]);
#pragma unroll
            for (int i = 0; i < 4; i++)
                bno[i] = make_float4(bn[4 * i + 0], bn[4 * i + 1], bn[4 * i + 2], bn[4 * i + 3]);
        }
    }

    // as = bn @ W1s (sender half), registers
    float as[32];
#pragma unroll
    for (int k = 0; k < 32; k++) as[k] = 0.0f;
#pragma unroll
    for (int j = 0; j < 16; j++) {
        float bj = bn[j];
        const float* wrow = &sW1[(16 + j) * 32];
#pragma unroll
        for (int k = 0; k < 32; k++) as[k] += bj * wrow[k];
    }
    __syncthreads();

    // cooperative Ar for the 16 receivers: thread -> (node, k-quad)
    {
        const int node = t & 15;
        const int k0 = (t >> 4) * 4;
        float a0 = sb1[k0 + 0], a1 = sb1[k0 + 1], a2 = sb1[k0 + 2], a3 = sb1[k0 + 3];
        const float* bnrow = &sBn[r0 + node][0];
#pragma unroll
        for (int j = 0; j < 16; j++) {
            float bj = bnrow[j];
            const float* wrow = &sW1[j * 32 + k0];
            a0 += bj * wrow[0];
            a1 += bj * wrow[1];
            a2 += bj * wrow[2];
            a3 += bj * wrow[3];
        }
        sAr[node][k0 + 0] = a0;
        sAr[node][k0 + 1] = a1;
        sAr[node][k0 + 2] = a2;
        sAr[node][k0 + 3] = a3;
    }
    __syncthreads();

#pragma unroll 1
    for (int rr = 0; rr < RT; rr++) {
        const float4* a4 = reinterpret_cast<const float4*>(&sAr[rr][0]);

        unsigned h1p[8];
#pragma unroll
        for (int j = 0; j < 8; j++) {
            float4 av = a4[j];     // broadcast LDS
            unsigned u0 = cvt_u8(av.x + as[4 * j + 0]);
            unsigned u1 = cvt_u8(av.y + as[4 * j + 1]);
            unsigned u2 = cvt_u8(av.z + as[4 * j + 2]);
            unsigned u3 = cvt_u8(av.w + as[4 * j + 3]);
            h1p[j] = pk4(u0, u1, u2, u3);
        }

        unsigned h2p[4];
#pragma unroll
        for (int g = 0; g < 4; g++) {
            const int nk = (g < 3) ? 4 : 3;
            unsigned qg[4];
#pragma unroll
            for (int u = 0; u < 4; u++) {
                if (u < nk) {
                    int k = g * 4 + u;
                    const uint4* w = reinterpret_cast<const uint4*>(&sEw.W2p[k][0]);
                    uint4 wa = w[0], wb = w[1];
                    int acc = sEw.b2i[k];
                    acc = dp4a_us(h1p[0], wa.x, acc);
                    acc = dp4a_us(h1p[1], wa.y, acc);
                    acc = dp4a_us(h1p[2], wa.z, acc);
                    acc = dp4a_us(h1p[3], wa.w, acc);
                    acc = dp4a_us(h1p[4], wb.x, acc);
                    acc = dp4a_us(h1p[5], wb.y, acc);
                    acc = dp4a_us(h1p[6], wb.z, acc);
                    acc = dp4a_us(h1p[7], wb.w, acc);
                    qg[u] = requant(acc);
                } else {
                    qg[u] = 0u;
                }
            }
            h2p[g] = pk4(qg[0], qg[1], qg[2], qg[3]);
        }

        unsigned e[6];
#pragma unroll
        for (int c = 0; c < 6; c++) {
            uint4 w = *reinterpret_cast<const uint4*>(&sEw.W3p[c][0]);
            int acc = sEw.b3i[c];
            acc = dp4a_us(h2p[0], w.x, acc);
            acc = dp4a_us(h2p[1], w.y, acc);
            acc = dp4a_us(h2p[2], w.z, acc);
            acc = dp4a_us(h2p[3], w.w, acc);
            e[c] = requant(acc);
        }
        const bool diag = (t == r0 + rr);
        int p01 = diag ? 0 : (int)__byte_perm(e[0], e[1], 0x7430);
        int p23 = diag ? 0 : (int)__byte_perm(e[2], e[3], 0x7430);
        int p45 = diag ? 0 : (int)__byte_perm(e[4], e[5], 0x7430);
        p01 = __reduce_add_sync(0xffffffffu, p01);
        p23 = __reduce_add_sync(0xffffffffu, p23);
        p45 = __reduce_add_sync(0xffffffffu, p45);
        if ((t & 31) == 0) {
            atomicAdd(&sEffI[rr][0], p01);
            atomicAdd(&sEffI[rr][1], p23);
            atomicAdd(&sEffI[rr][2], p45);
        }
    }
    __syncthreads();

    if (t < RT * 6) {
        int node = t / 6, c = t % 6;
        int v = sEffI[node][c >> 1];
        float ef = (float)((c & 1) ? ((v >> 16) & 0xFFFF) : (v & 0xFFFF));
        g_eff[(size_t)(b * NN + r0 + node) * 6 + c] = ef;
    }
}

// ---------------------------------------------------------------------------
// node_post kernel: 256 threads = (node, role 0/1). Prefolded contiguous
// weight copy (no in-kernel fold); neuron-split fo layers with u8 smem
// exchange (exact integer activations, bit-identical accumulation order).
// ---------------------------------------------------------------------------
struct FoW {
    float Wo1s[22][48]; float bo1[48];
    float Wo2s[45][24]; float bo2[24];
    float Wo3s[22][8];  float bo3[8];
};

__global__ void __launch_bounds__(256) node_post_kernel(float* __restrict__ out)
{
    __shared__ __align__(16) FoW sFo;
    __shared__ unsigned char sH1[NN][52];   // stride 52: gcd(13,32)=1
    __shared__ unsigned char sH2[NN][28];   // stride 28: gcd(7,32)=1
    __shared__ unsigned char sGv[NN][8];
    __shared__ int sPoolI[4];
    __shared__ float sPl[8];
    __shared__ float sc1[48];
    __shared__ float sl[5];

    const int t = threadIdx.x, b = blockIdx.x;

    {
        const uint4* fs = reinterpret_cast<const uint4*>(&g_qw.Wo1s[0][0]);
        uint4* fd = reinterpret_cast<uint4*>(&sFo);
        for (int i = t; i < 598; i += 256) fd[i] = fs[i];
        if (t < 4) sPoolI[t] = 0;
    }
    __syncthreads();

    const int n = t & 127;
    const int role = t >> 7;   // 0 or 1

    float bn[16];
    {
        const float4* p = reinterpret_cast<const float4*>(&g_bn[(size_t)(b * NN + n) * 16]);
#pragma unroll
        for (int i = 0; i < 4; i++) {
            float4 v = p[i];
            bn[4 * i + 0] = v.x; bn[4 * i + 1] = v.y;
            bn[4 * i + 2] = v.z; bn[4 * i + 3] = v.w;
        }
    }
    float eff[6];
    {
        const float* ep = &g_eff[(size_t)(b * NN + n) * 6];
#pragma unroll
        for (int c = 0; c < 6; c++) eff[c] = ep[c];
    }

    // fo layer 1: role 0 -> k [0,23), role 1 -> k [23,45)
    {
        const int k0 = role ? 23 : 0;
        const int k1 = role ? 45 : 23;
        for (int k = k0; k < k1; k++) {
            float a = sFo.bo1[k];
#pragma unroll
            for (int j = 0; j < 16; j++) a += bn[j] * sFo.Wo1s[j][k];
#pragma unroll
            for (int c = 0; c < 6; c++) a += eff[c] * sFo.Wo1s[16 + c][k];
            sH1[n][k] = (unsigned char)cvt_u8(a);
        }
    }
    __syncthreads();

    // fo layer 2: role 0 -> k [0,11), role 1 -> k [11,22)
    {
        const int k0 = role ? 11 : 0;
        const int k1 = role ? 22 : 11;
        float h1f[45];
#pragma unroll
        for (int j = 0; j < 45; j++) h1f[j] = (float)sH1[n][j];
        for (int k = k0; k < k1; k++) {
            float a = sFo.bo2[k];
#pragma unroll
            for (int j = 0; j < 45; j++) a += h1f[j] * sFo.Wo2s[j][k];
            sH2[n][k] = (unsigned char)cvt_u8(a);
        }
    }
    __syncthreads();

    // fo layer 3: role 0 -> c 0..2, role 1 -> c 3..5
    {
        float h2f[22];
#pragma unroll
        for (int j = 0; j < 22; j++) h2f[j] = (float)sH2[n][j];
#pragma unroll
        for (int cc = 0; cc < 3; cc++) {
            int c = role * 3 + cc;
            float a = sFo.bo3[c];
#pragma unroll
            for (int j = 0; j < 22; j++) a += h2f[j] * sFo.Wo3s[j][c];
            sGv[n][c] = (unsigned char)cvt_u8(a);
        }
    }
    __syncthreads();

    // exact packed-int pooling over 128 nodes (t < 128 only)
    if (t < 128) {
        int gv[6];
#pragma unroll
        for (int c = 0; c < 6; c++) gv[c] = (int)sGv[t][c];
        int p01 = gv[0] | (gv[1] << 16);
        int p23 = gv[2] | (gv[3] << 16);
        int p45 = gv[4] | (gv[5] << 16);
        p01 = __reduce_add_sync(0xffffffffu, p01);
        p23 = __reduce_add_sync(0xffffffffu, p23);
        p45 = __reduce_add_sync(0xffffffffu, p45);
        if ((t & 31) == 0) {
            atomicAdd(&sPoolI[0], p01);
            atomicAdd(&sPoolI[1], p23);
            atomicAdd(&sPoolI[2], p45);
        }
    }
    __syncthreads();
    if (t < 6) {
        int v = sPoolI[t >> 1];
        sPl[t] = (float)((t & 1) ? ((v >> 16) & 0xFFFF) : (v & 0xFFFF));
    }
    __syncthreads();

    // head (weights via L2 — proven cheap in R15)
    if (t < 48) {
        float a = g_qw.bc1[t];
#pragma unroll
        for (int c = 0; c < 6; c++) a += sPl[c] * g_qw.Wc1t[t][c];
        sc1[t] = qreluF(a);
    }
    __syncthreads();
    if (t < 5) {
        float a = g_qw.bc2[t];
#pragma unroll
        for (int k = 0; k < 48; k++) a += sc1[k] * g_qw.Wc2t[t][k];
        sl[t] = a;
    }
    __syncthreads();
    if (t == 0) {
        float m = sl[0];
#pragma unroll
        for (int k = 1; k < 5; k++) m = fmaxf(m, sl[k]);
        float ex[5], sum = 0.0f;
#pragma unroll
        for (int k = 0; k < 5; k++) { ex[k] = expf(sl[k] - m); sum += ex[k]; }
        float inv = 1.0f / sum;
#pragma unroll
        for (int k = 0; k < 5; k++) out[b * 5 + k] = ex[k] * inv;
    }
}

// ---------------------------------------------------------------------------
extern "C" void kernel_launch(void* const* d_in, const int* in_sizes, int n_in,
                              void* d_out, int out_size)
{
    (void)in_sizes; (void)n_in; (void)out_size;

    dim3 grid(RGF + 1, BB);
    edge_kernel<<<grid, 128>>>(
        (const float*)d_in[0],
        (const float*)d_in[1],  (const float*)d_in[2],
        (const float*)d_in[3],  (const float*)d_in[4],
        (const float*)d_in[5],  (const float*)d_in[6],
        (const float*)d_in[7],  (const float*)d_in[8],
        (const float*)d_in[9],  (const float*)d_in[10],
        (const float*)d_in[11], (const float*)d_in[12],
        (const float*)d_in[13], (const float*)d_in[14],
        (const float*)d_in[15], (const float*)d_in[16],
        (const float*)d_in[17], (const float*)d_in[18],
        (const float*)d_in[19], (const float*)d_in[20]);

    node_post_kernel<<<BB, 256>>>((float*)d_out);
}

// round 17
// speedup vs baseline: 1.0334x; 1.0334x over previous
#include <cuda_runtime.h>
#include <math.h>

#define BB 128
#define NN 128
#define RT 32
#define RGF (NN / RT)   // 4: fold-column index in edge grid

// Folded fo + head weights (written by edge kernel's piggyback blocks).
struct QWeights {
    float Wo1s[22][48];   // [j][k]: j<16 scaled x256, j=16..21 x1; k>=45 pad 0
    float bo1[48];
    float Wo2s[45][24];   // [j][k], k>=22 pad 0
    float bo2[24];
    float Wo3s[22][8];    // [j][c], c>=6 pad 0
    float bo3[8];
    float Wc1t[48][8];
    float bc1[48];
    float Wc2t[5][48];
    float bc2[8];
};

__device__ QWeights g_qw;
__device__ __align__(16) float g_bn[BB * NN * 16];
__device__ __align__(16) float g_eff[BB * NN * 6];

__device__ __forceinline__ float qb(float x) {
    float y = fminf(fmaxf(x, -1.0f), 127.0f / 128.0f);
    return rintf(y * 128.0f) * (1.0f / 128.0f);
}
__device__ __forceinline__ int qm(float x) {
    float y = fminf(fmaxf(x, -1.0f), 127.0f / 128.0f);
    return (int)rintf(y * 128.0f);
}
__device__ __forceinline__ float qreluF(float p) {
    return rintf(fminf(fmaxf(p, 0.0f), 255.0f));
}
__device__ __forceinline__ unsigned cvt_u8(float x) {
    unsigned short h;
    asm("cvt.rni.sat.u8.f32 %0, %1;" : "=h"(h) : "f"(x));
    return (unsigned)h;
}
__device__ __forceinline__ unsigned requant(int acc) {
    return cvt_u8((float)acc * (1.0f / 128.0f));
}
__device__ __forceinline__ unsigned pk4(unsigned a, unsigned b, unsigned c, unsigned d) {
    return __byte_perm(__byte_perm(a, b, 0x0040), __byte_perm(c, d, 0x0040), 0x5410);
}
__device__ __forceinline__ int dp4a_us(unsigned a, unsigned b, int c) {
    int d;
    asm("dp4a.u32.s32 %0, %1, %2, %3;" : "=r"(d) : "r"(a), "r"(b), "r"(c));
    return d;
}

// ---------------------------------------------------------------------------
// edge kernel: grid (RGF+1, BB). RT=32 receivers per block: half the blocks
// of RT=16 -> single wave at ~4 blocks/SM, and half the per-block prologue
// overhead (W1 fold, bn, as-compute) across the chip.
//   rg < RGF : edge path (bn/Ar/As inline, dp4a main loop -> g_eff)
//   rg == RGF, b < 4 : fold fo + head weights -> g_qw
// ---------------------------------------------------------------------------
struct EdgeW { unsigned W2p[15][8]; int b2i[16]; unsigned W3p[6][4]; int b3i[8]; };

__global__ void __launch_bounds__(128) edge_kernel(
    const float* __restrict__ x,
    const float* __restrict__ gamma, const float* __restrict__ beta,
    const float* __restrict__ mean,  const float* __restrict__ var,
    const float* __restrict__ fr_w1, const float* __restrict__ fr_b1,
    const float* __restrict__ fr_w2, const float* __restrict__ fr_b2,
    const float* __restrict__ fr_w3, const float* __restrict__ fr_b3,
    const float* __restrict__ fo_w1, const float* __restrict__ fo_b1,
    const float* __restrict__ fo_w2, const float* __restrict__ fo_b2,
    const float* __restrict__ fo_w3, const float* __restrict__ fo_b3,
    const float* __restrict__ fc_w1, const float* __restrict__ fc_b1,
    const float* __restrict__ fc_w2, const float* __restrict__ fc_b2)
{
    const int t = threadIdx.x;
    const int rg = blockIdx.x, b = blockIdx.y;

    if (rg == RGF) {
        if (b == 0) {
            for (int i = t; i < 22 * 48; i += 128) {
                int j = i / 48, k = i % 48;
                float v = (k < 45) ? qb(fo_w1[j * 45 + k]) : 0.0f;
                g_qw.Wo1s[j][k] = (j < 16) ? 256.0f * v : v;
            }
            if (t < 48) g_qw.bo1[t] = (t < 45) ? 256.0f * qb(fo_b1[t]) : 0.0f;
        } else if (b == 1) {
            for (int i = t; i < 45 * 24; i += 128) {
                int j = i / 24, k = i % 24;
                g_qw.Wo2s[j][k] = (k < 22) ? qb(fo_w2[j * 22 + k]) : 0.0f;
            }
            if (t < 24) g_qw.bo2[t] = (t < 22) ? 256.0f * qb(fo_b2[t]) : 0.0f;
        } else if (b == 2) {
            for (int i = t; i < 22 * 8; i += 128) {
                int j = i / 8, c = i % 8;
                g_qw.Wo3s[j][c] = (c < 6) ? qb(fo_w3[j * 6 + c]) : 0.0f;
            }
            if (t < 8) g_qw.bo3[t] = (t < 6) ? 256.0f * qb(fo_b3[t]) : 0.0f;
            for (int i = t; i < 48 * 8; i += 128) {
                int k = i / 8, c = i % 8;
                g_qw.Wc1t[k][c] = (c < 6) ? qb(fc_w1[c * 48 + k]) : 0.0f;
            }
            if (t < 48) g_qw.bc1[t] = 256.0f * qb(fc_b1[t]);
        } else if (b == 3) {
            for (int i = t; i < 5 * 48; i += 128) {
                int o = i / 48, k = i % 48;
                g_qw.Wc2t[o][k] = qb(fc_w2[k * 5 + o]) * (1.0f / 256.0f);
            }
            if (t < 8) g_qw.bc2[t] = (t < 5) ? qb(fc_b2[t]) : 0.0f;
        }
        return;
    }

    __shared__ __align__(16) float sW1[32 * 32];
    __shared__ float sb1[32];
    __shared__ float sA[16], sB[16];
    __shared__ float sBn[NN][17];
    __shared__ __align__(16) EdgeW sEw;
    __shared__ __align__(16) float sAr[RT][36];
    __shared__ int sEffI[RT][4];

    const int r0 = rg * RT;

    for (int i = t; i < 1024; i += 128) {
        int j = i >> 5, k = i & 31;
        sW1[i] = (k < 30) ? 256.0f * qb(fr_w1[j * 30 + k]) : 0.0f;
    }
    if (t < 120) {
        int k = t / 8, j4 = t % 8;
        unsigned p = 0;
#pragma unroll
        for (int u = 0; u < 4; u++) {
            int j = j4 * 4 + u;
            int m = (j < 30) ? qm(fr_w2[j * 15 + k]) : 0;
            p |= ((unsigned)(m & 255)) << (8 * u);
        }
        sEw.W2p[k][j4] = p;
    }
    if (t >= 120 && t < 126) sEw.b3i[t - 120] = 256 * qm(fr_b3[t - 120]);
    if (t < 24) {
        int c = t / 4, j4 = t % 4;
        unsigned p = 0;
#pragma unroll
        for (int u = 0; u < 4; u++) {
            int j = j4 * 4 + u;
            int m = (j < 15) ? qm(fr_w3[j * 6 + c]) : 0;
            p |= ((unsigned)(m & 255)) << (8 * u);
        }
        sEw.W3p[c][j4] = p;
    }
    if (t < 16) sEw.b2i[t] = (t < 15) ? 256 * qm(fr_b2[t]) : 0;
    if (t < 32) sb1[t] = (t < 30) ? 256.0f * qb(fr_b1[t]) : 0.0f;
    if (t < 16) {
        float s = gamma[t] / sqrtf(var[t] + 1e-3f);
        sA[t] = s;
        sB[t] = beta[t] - mean[t] * s;
    }
    for (int i = t; i < RT * 4; i += 128) (&sEffI[0][0])[i] = 0;
    __syncthreads();

    float bn[16];
    {
        const float4* xp = reinterpret_cast<const float4*>(x + (size_t)(b * NN + t) * 16);
#pragma unroll
        for (int i = 0; i < 4; i++) {
            float4 v = xp[i];
            bn[4 * i + 0] = v.x * sA[4 * i + 0] + sB[4 * i + 0];
            bn[4 * i + 1] = v.y * sA[4 * i + 1] + sB[4 * i + 1];
            bn[4 * i + 2] = v.z * sA[4 * i + 2] + sB[4 * i + 2];
            bn[4 * i + 3] = v.w * sA[4 * i + 3] + sB[4 * i + 3];
        }
#pragma unroll
        for (int j = 0; j < 16; j++) sBn[t][j] = bn[j];
        if (rg == 0) {
            float4* bno = reinterpret_cast<float4*>(&g_bn[(size_t)(b * NN + t) * 16]);
#pragma unroll
            for (int i = 0; i < 4; i++)
                bno[i] = make_float4(bn[4 * i + 0], bn[4 * i + 1], bn[4 * i + 2], bn[4 * i + 3]);
        }
    }

    // as = bn @ W1s (sender half), registers
    float as[32];
#pragma unroll
    for (int k = 0; k < 32; k++) as[k] = 0.0f;
#pragma unroll
    for (int j = 0; j < 16; j++) {
        float bj = bn[j];
        const float* wrow = &sW1[(16 + j) * 32];
#pragma unroll
        for (int k = 0; k < 32; k++) as[k] += bj * wrow[k];
    }
    __syncthreads();

    // cooperative Ar for the 32 receivers: thread -> (node, 8-k group)
    {
        const int node = t & 31;
        const int k0 = (t >> 5) * 8;
        float acc[8];
#pragma unroll
        for (int u = 0; u < 8; u++) acc[u] = sb1[k0 + u];
        const float* bnrow = &sBn[r0 + node][0];
#pragma unroll
        for (int j = 0; j < 16; j++) {
            float bj = bnrow[j];
            const float* wrow = &sW1[j * 32 + k0];
#pragma unroll
            for (int u = 0; u < 8; u++) acc[u] += bj * wrow[u];
        }
#pragma unroll
        for (int u = 0; u < 8; u++) sAr[node][k0 + u] = acc[u];
    }
    __syncthreads();

#pragma unroll 1
    for (int rr = 0; rr < RT; rr++) {
        const float4* a4 = reinterpret_cast<const float4*>(&sAr[rr][0]);

        unsigned h1p[8];
#pragma unroll
        for (int j = 0; j < 8; j++) {
            float4 av = a4[j];     // broadcast LDS
            unsigned u0 = cvt_u8(av.x + as[4 * j + 0]);
            unsigned u1 = cvt_u8(av.y + as[4 * j + 1]);
            unsigned u2 = cvt_u8(av.z + as[4 * j + 2]);
            unsigned u3 = cvt_u8(av.w + as[4 * j + 3]);
            h1p[j] = pk4(u0, u1, u2, u3);
        }

        unsigned h2p[4];
#pragma unroll
        for (int g = 0; g < 4; g++) {
            const int nk = (g < 3) ? 4 : 3;
            unsigned qg[4];
#pragma unroll
            for (int u = 0; u < 4; u++) {
                if (u < nk) {
                    int k = g * 4 + u;
                    const uint4* w = reinterpret_cast<const uint4*>(&sEw.W2p[k][0]);
                    uint4 wa = w[0], wb = w[1];
                    int acc = sEw.b2i[k];
                    acc = dp4a_us(h1p[0], wa.x, acc);
                    acc = dp4a_us(h1p[1], wa.y, acc);
                    acc = dp4a_us(h1p[2], wa.z, acc);
                    acc = dp4a_us(h1p[3], wa.w, acc);
                    acc = dp4a_us(h1p[4], wb.x, acc);
                    acc = dp4a_us(h1p[5], wb.y, acc);
                    acc = dp4a_us(h1p[6], wb.z, acc);
                    acc = dp4a_us(h1p[7], wb.w, acc);
                    qg[u] = requant(acc);
                } else {
                    qg[u] = 0u;
                }
            }
            h2p[g] = pk4(qg[0], qg[1], qg[2], qg[3]);
        }

        unsigned e[6];
#pragma unroll
        for (int c = 0; c < 6; c++) {
            uint4 w = *reinterpret_cast<const uint4*>(&sEw.W3p[c][0]);
            int acc = sEw.b3i[c];
            acc = dp4a_us(h2p[0], w.x, acc);
            acc = dp4a_us(h2p[1], w.y, acc);
            acc = dp4a_us(h2p[2], w.z, acc);
            acc = dp4a_us(h2p[3], w.w, acc);
            e[c] = requant(acc);
        }
        const bool diag = (t == r0 + rr);
        int p01 = diag ? 0 : (int)__byte_perm(e[0], e[1], 0x7430);
        int p23 = diag ? 0 : (int)__byte_perm(e[2], e[3], 0x7430);
        int p45 = diag ? 0 : (int)__byte_perm(e[4], e[5], 0x7430);
        p01 = __reduce_add_sync(0xffffffffu, p01);
        p23 = __reduce_add_sync(0xffffffffu, p23);
        p45 = __reduce_add_sync(0xffffffffu, p45);
        if ((t & 31) == 0) {
            atomicAdd(&sEffI[rr][0], p01);
            atomicAdd(&sEffI[rr][1], p23);
            atomicAdd(&sEffI[rr][2], p45);
        }
    }
    __syncthreads();

    // unpack 16-bit halves (each sum <= 127*255 < 2^15) -> g_eff
    for (int i = t; i < RT * 6; i += 128) {
        int node = i / 6, c = i % 6;
        int v = sEffI[node][c >> 1];
        float ef = (float)((c & 1) ? ((v >> 16) & 0xFFFF) : (v & 0xFFFF));
        g_eff[(size_t)(b * NN + r0 + node) * 6 + c] = ef;
    }
}

// ---------------------------------------------------------------------------
// node_post kernel (R15-proven, 12.6us): 128 threads, one node/thread,
// contiguous uint4 copy of pre-folded fo weights; head weights via L2.
// ---------------------------------------------------------------------------
struct FoW {
    float Wo1s[22][48]; float bo1[48];
    float Wo2s[45][24]; float bo2[24];
    float Wo3s[22][8];  float bo3[8];
};

__global__ void __launch_bounds__(128) node_post_kernel(float* __restrict__ out)
{
    __shared__ __align__(16) FoW sFo;
    __shared__ int sPoolI[4];
    __shared__ float sPl[8];
    __shared__ float sc1[48];
    __shared__ float sl[5];

    const int t = threadIdx.x, b = blockIdx.x;

    {
        const uint4* fs = reinterpret_cast<const uint4*>(&g_qw.Wo1s[0][0]);
        uint4* fd = reinterpret_cast<uint4*>(&sFo);
        for (int i = t; i < 598; i += 128) fd[i] = fs[i];
        if (t < 4) sPoolI[t] = 0;
    }
    __syncthreads();

    const int n = t;
    float bn[16];
    {
        const float4* p = reinterpret_cast<const float4*>(&g_bn[(size_t)(b * NN + n) * 16]);
#pragma unroll
        for (int i = 0; i < 4; i++) {
            float4 v = p[i];
            bn[4 * i + 0] = v.x; bn[4 * i + 1] = v.y;
            bn[4 * i + 2] = v.z; bn[4 * i + 3] = v.w;
        }
    }
    float eff[6];
    {
        const float* ep = &g_eff[(size_t)(b * NN + n) * 6];
#pragma unroll
        for (int c = 0; c < 6; c++) eff[c] = ep[c];
    }

    float h1[45];
#pragma unroll
    for (int k = 0; k < 45; k++) {
        float a = sFo.bo1[k];
#pragma unroll
        for (int j = 0; j < 16; j++) a += bn[j] * sFo.Wo1s[j][k];
#pragma unroll
        for (int c = 0; c < 6; c++) a += eff[c] * sFo.Wo1s[16 + c][k];
        h1[k] = qreluF(a);
    }
    float h2[22];
#pragma unroll
    for (int k = 0; k < 22; k++) {
        float a = sFo.bo2[k];
#pragma unroll
        for (int j = 0; j < 45; j++) a += h1[j] * sFo.Wo2s[j][k];
        h2[k] = qreluF(a);
    }
    int gv[6];
#pragma unroll
    for (int c = 0; c < 6; c++) {
        float a = sFo.bo3[c];
#pragma unroll
        for (int j = 0; j < 22; j++) a += h2[j] * sFo.Wo3s[j][c];
        gv[c] = (int)qreluF(a);
    }

    int p01 = gv[0] | (gv[1] << 16);
    int p23 = gv[2] | (gv[3] << 16);
    int p45 = gv[4] | (gv[5] << 16);
    p01 = __reduce_add_sync(0xffffffffu, p01);
    p23 = __reduce_add_sync(0xffffffffu, p23);
    p45 = __reduce_add_sync(0xffffffffu, p45);
    if ((t & 31) == 0) {
        atomicAdd(&sPoolI[0], p01);
        atomicAdd(&sPoolI[1], p23);
        atomicAdd(&sPoolI[2], p45);
    }
    __syncthreads();
    if (t < 6) {
        int v = sPoolI[t >> 1];
        sPl[t] = (float)((t & 1) ? ((v >> 16) & 0xFFFF) : (v & 0xFFFF));
    }
    __syncthreads();

    if (t < 48) {
        float a = g_qw.bc1[t];
#pragma unroll
        for (int c = 0; c < 6; c++) a += sPl[c] * g_qw.Wc1t[t][c];
        sc1[t] = qreluF(a);
    }
    __syncthreads();
    if (t < 5) {
        float a = g_qw.bc2[t];
#pragma unroll
        for (int k = 0; k < 48; k++) a += sc1[k] * g_qw.Wc2t[t][k];
        sl[t] = a;
    }
    __syncthreads();
    if (t == 0) {
        float m = sl[0];
#pragma unroll
        for (int k = 1; k < 5; k++) m = fmaxf(m, sl[k]);
        float ex[5], sum = 0.0f;
#pragma unroll
        for (int k = 0; k < 5; k++) { ex[k] = expf(sl[k] - m); sum += ex[k]; }
        float inv = 1.0f / sum;
#pragma unroll
        for (int k = 0; k < 5; k++) out[b * 5 + k] = ex[k] * inv;
    }
}

// ---------------------------------------------------------------------------
extern "C" void kernel_launch(void* const* d_in, const int* in_sizes, int n_in,
                              void* d_out, int out_size)
{
    (void)in_sizes; (void)n_in; (void)out_size;

    dim3 grid(RGF + 1, BB);
    edge_kernel<<<grid, 128>>>(
        (const float*)d_in[0],
        (const float*)d_in[1],  (const float*)d_in[2],
        (const float*)d_in[3],  (const float*)d_in[4],
        (const float*)d_in[5],  (const float*)d_in[6],
        (const float*)d_in[7],  (const float*)d_in[8],
        (const float*)d_in[9],  (const float*)d_in[10],
        (const float*)d_in[11], (const float*)d_in[12],
        (const float*)d_in[13], (const float*)d_in[14],
        (const float*)d_in[15], (const float*)d_in[16],
        (const float*)d_in[17], (const float*)d_in[18],
        (const float*)d_in[19], (const float*)d_in[20]);

    node_post_kernel<<<BB, 128>>>((float*)d_out);
}